// round 12
// baseline (speedup 1.0000x reference)
#include <cuda_runtime.h>
#include <cuda_bf16.h>
#include <cstdint>

// GlobalQuantizedLatent: per-element scalar quantization vs 16-entry codebook.
// Output = 4 contiguous fp32 streams [x, quantized, z_hat, indices(float)].
//
// FINAL — converged at the HBM roofline after an 11-round lever sweep.
// Best measured: harness 54.37us / kernel 49.44us / DRAM 70.6% / rel_err 0.0
// (same binary re-benched: 55.30/49.92/69.9% -> run-to-run noise ~ +-1us).
//
//  - 256 threads/block, 2 front-batched independent float8 chunks per thread
//    (MLP saturates at 2; 4 chunks and 512-thread blocks measured worse)
//  - 256-bit (.v8) global loads/stores with evict-first .cs hints
//  - x-passthrough store issued immediately after each load (overlaps compute)
//  - exact argmin: closed-form candidate k0 = round((x+0.5)*15) + first-min-
//    wins tie-break over {k0-1,k0,k0+1} == jnp.argmin over all 16 values
//
// Roofline: 320MB mandatory traffic @ ~6.5TB/s effective = practical HBM
// ceiling for this 1:4 read:write mix. Eleven structural variants bracket at
// 67-70.6% DRAM-active with L2/L1/issue idle.

__device__ __forceinline__ void ld256cs(const float* __restrict__ p, float* v) {
    asm volatile("ld.global.cs.v8.f32 {%0,%1,%2,%3,%4,%5,%6,%7}, [%8];"
                 : "=f"(v[0]), "=f"(v[1]), "=f"(v[2]), "=f"(v[3]),
                   "=f"(v[4]), "=f"(v[5]), "=f"(v[6]), "=f"(v[7])
                 : "l"(p));
}

__device__ __forceinline__ void st256cs(float* __restrict__ p, const float* v) {
    asm volatile("st.global.cs.v8.f32 [%0], {%1,%2,%3,%4,%5,%6,%7,%8};"
                 :: "l"(p),
                    "f"(v[0]), "f"(v[1]), "f"(v[2]), "f"(v[3]),
                    "f"(v[4]), "f"(v[5]), "f"(v[6]), "f"(v[7])
                 : "memory");
}

__device__ __forceinline__ int quantize_one(float x, const float* __restrict__ sv,
                                            float& q_out) {
    float s = __fmaf_rn(x, 15.0f, 7.5f);      // (x + 0.5) * 15
    int k0 = __float2int_rn(s);
    k0 = min(max(k0, 0), 15);
    int km = max(k0 - 1, 0);
    int kp = min(k0 + 1, 15);

    // first-min-wins argmin over {km,k0,kp} == jnp.argmin over all 16
    float vkm = sv[km], vk0 = sv[k0], vkp = sv[kp];
    float dbest = fabsf(x - vkm);
    int   bi    = km;
    float qv    = vkm;

    float d1 = fabsf(x - vk0);
    if (d1 < dbest) { dbest = d1; bi = k0; qv = vk0; }

    float d2 = fabsf(x - vkp);
    if (d2 < dbest) { bi = kp; qv = vkp; }

    q_out = qv;
    return bi;
}

__device__ __forceinline__ void emit8_rest(float* __restrict__ out_q,
                                           float* __restrict__ out_zh,
                                           float* __restrict__ out_idx,
                                           int base, const float* xv,
                                           const float* __restrict__ sv) {
    float qv[8], zh[8], iv[8];
    #pragma unroll
    for (int j = 0; j < 8; j++) {
        int b = quantize_one(xv[j], sv, qv[j]);
        zh[j] = __fadd_rn(xv[j], __fsub_rn(qv[j], xv[j]));
        iv[j] = (float)b;
    }
    st256cs(out_q   + base, qv);
    st256cs(out_zh  + base, zh);
    st256cs(out_idx + base, iv);
}

__global__ void __launch_bounds__(256)
gql_kernel(const float* __restrict__ x,
           const float* __restrict__ values,
           float* __restrict__ out,
           int n)
{
    __shared__ float sv[16];
    if (threadIdx.x < 16) sv[threadIdx.x] = values[threadIdx.x];
    __syncthreads();

    float* __restrict__ out_x   = out;
    float* __restrict__ out_q   = out + (size_t)n;
    float* __restrict__ out_zh  = out + 2 * (size_t)n;
    float* __restrict__ out_idx = out + 3 * (size_t)n;

    const int n8 = n >> 3;
    int i8a = blockIdx.x * (blockDim.x * 2) + threadIdx.x;   // float8 index
    int i8b = i8a + blockDim.x;
    const int basea = i8a * 8;
    const int baseb = i8b * 8;

    bool va = (i8a < n8), vb = (i8b < n8);
    float xa[8], xb[8];
    // front-batched loads (MLP = 2)
    if (va) ld256cs(x + basea, xa);
    if (vb) ld256cs(x + baseb, xb);

    // passthrough stores depend only on the loads — issue before compute
    if (va) st256cs(out_x + basea, xa);
    if (vb) st256cs(out_x + baseb, xb);

    if (va) emit8_rest(out_q, out_zh, out_idx, basea, xa, sv);
    if (vb) emit8_rest(out_q, out_zh, out_idx, baseb, xb, sv);

    // scalar tail (n not divisible by 8) — not hit for N=16M
    if (blockIdx.x == 0 && threadIdx.x < (n & 7)) {
        int t = (n8 << 3) + threadIdx.x;
        float xi = x[t];
        float q;
        int b = quantize_one(xi, sv, q);
        out_x[t]   = xi;
        out_q[t]   = q;
        out_zh[t]  = __fadd_rn(xi, __fsub_rn(q, xi));
        out_idx[t] = (float)b;
    }
}

extern "C" void kernel_launch(void* const* d_in, const int* in_sizes, int n_in,
                              void* d_out, int out_size) {
    const float* x      = (const float*)d_in[0];
    const float* values = (const float*)d_in[1];
    float* out = (float*)d_out;
    int n = in_sizes[0];

    int n8 = (n + 7) / 8;
    int threads = 256;
    int per_block = threads * 2;
    int blocks = (n8 + per_block - 1) / per_block;
    if (blocks < 1) blocks = 1;
    gql_kernel<<<blocks, threads>>>(x, values, out, n);
}

// round 13
// speedup vs baseline: 1.0064x; 1.0064x over previous
#include <cuda_runtime.h>
#include <cuda_bf16.h>
#include <cstdint>

// GlobalQuantizedLatent: per-element scalar quantization vs 16-entry codebook.
// Output = 4 contiguous fp32 streams [x, quantized, z_hat, indices(float)].
//
// FINAL — converged at the HBM roofline after a 12-round lever sweep.
// Identical-binary repeats: harness 54.37/55.30/55.58us, kernel
// 49.44/49.92/50.30us, DRAM 70.6/69.9/69.3% -> noise sigma ~0.5us.
//
//  - 256 threads/block, 2 front-batched independent float8 chunks per thread
//    (MLP saturates at 2; 4 chunks and 512-thread blocks measured worse)
//  - 256-bit (.v8) global loads/stores with evict-first .cs hints
//  - x-passthrough store issued immediately after each load (overlaps compute)
//  - exact argmin: closed-form candidate k0 = round((x+0.5)*15) + first-min-
//    wins tie-break over {k0-1,k0,k0+1} == jnp.argmin over all 16 values
//
// Roofline: 320MB mandatory traffic @ ~6.5TB/s effective = practical HBM
// ceiling for this 1:4 read:write mix. Twelve structural variants bracket at
// 67-70.6% DRAM-active with L2/L1/issue idle. Audited-and-rejected levers:
// CE-offload copy (+64MB traffic), TMA stores (LTS path-independent),
// arithmetic codebook (ALU not binding), occupancy forcing (32-81% occ flat).

__device__ __forceinline__ void ld256cs(const float* __restrict__ p, float* v) {
    asm volatile("ld.global.cs.v8.f32 {%0,%1,%2,%3,%4,%5,%6,%7}, [%8];"
                 : "=f"(v[0]), "=f"(v[1]), "=f"(v[2]), "=f"(v[3]),
                   "=f"(v[4]), "=f"(v[5]), "=f"(v[6]), "=f"(v[7])
                 : "l"(p));
}

__device__ __forceinline__ void st256cs(float* __restrict__ p, const float* v) {
    asm volatile("st.global.cs.v8.f32 [%0], {%1,%2,%3,%4,%5,%6,%7,%8};"
                 :: "l"(p),
                    "f"(v[0]), "f"(v[1]), "f"(v[2]), "f"(v[3]),
                    "f"(v[4]), "f"(v[5]), "f"(v[6]), "f"(v[7])
                 : "memory");
}

__device__ __forceinline__ int quantize_one(float x, const float* __restrict__ sv,
                                            float& q_out) {
    float s = __fmaf_rn(x, 15.0f, 7.5f);      // (x + 0.5) * 15
    int k0 = __float2int_rn(s);
    k0 = min(max(k0, 0), 15);
    int km = max(k0 - 1, 0);
    int kp = min(k0 + 1, 15);

    // first-min-wins argmin over {km,k0,kp} == jnp.argmin over all 16
    float vkm = sv[km], vk0 = sv[k0], vkp = sv[kp];
    float dbest = fabsf(x - vkm);
    int   bi    = km;
    float qv    = vkm;

    float d1 = fabsf(x - vk0);
    if (d1 < dbest) { dbest = d1; bi = k0; qv = vk0; }

    float d2 = fabsf(x - vkp);
    if (d2 < dbest) { bi = kp; qv = vkp; }

    q_out = qv;
    return bi;
}

__device__ __forceinline__ void emit8_rest(float* __restrict__ out_q,
                                           float* __restrict__ out_zh,
                                           float* __restrict__ out_idx,
                                           int base, const float* xv,
                                           const float* __restrict__ sv) {
    float qv[8], zh[8], iv[8];
    #pragma unroll
    for (int j = 0; j < 8; j++) {
        int b = quantize_one(xv[j], sv, qv[j]);
        zh[j] = __fadd_rn(xv[j], __fsub_rn(qv[j], xv[j]));
        iv[j] = (float)b;
    }
    st256cs(out_q   + base, qv);
    st256cs(out_zh  + base, zh);
    st256cs(out_idx + base, iv);
}

__global__ void __launch_bounds__(256)
gql_kernel(const float* __restrict__ x,
           const float* __restrict__ values,
           float* __restrict__ out,
           int n)
{
    __shared__ float sv[16];
    if (threadIdx.x < 16) sv[threadIdx.x] = values[threadIdx.x];
    __syncthreads();

    float* __restrict__ out_x   = out;
    float* __restrict__ out_q   = out + (size_t)n;
    float* __restrict__ out_zh  = out + 2 * (size_t)n;
    float* __restrict__ out_idx = out + 3 * (size_t)n;

    const int n8 = n >> 3;
    int i8a = blockIdx.x * (blockDim.x * 2) + threadIdx.x;   // float8 index
    int i8b = i8a + blockDim.x;
    const int basea = i8a * 8;
    const int baseb = i8b * 8;

    bool va = (i8a < n8), vb = (i8b < n8);
    float xa[8], xb[8];
    // front-batched loads (MLP = 2)
    if (va) ld256cs(x + basea, xa);
    if (vb) ld256cs(x + baseb, xb);

    // passthrough stores depend only on the loads — issue before compute
    if (va) st256cs(out_x + basea, xa);
    if (vb) st256cs(out_x + baseb, xb);

    if (va) emit8_rest(out_q, out_zh, out_idx, basea, xa, sv);
    if (vb) emit8_rest(out_q, out_zh, out_idx, baseb, xb, sv);

    // scalar tail (n not divisible by 8) — not hit for N=16M
    if (blockIdx.x == 0 && threadIdx.x < (n & 7)) {
        int t = (n8 << 3) + threadIdx.x;
        float xi = x[t];
        float q;
        int b = quantize_one(xi, sv, q);
        out_x[t]   = xi;
        out_q[t]   = q;
        out_zh[t]  = __fadd_rn(xi, __fsub_rn(q, xi));
        out_idx[t] = (float)b;
    }
}

extern "C" void kernel_launch(void* const* d_in, const int* in_sizes, int n_in,
                              void* d_out, int out_size) {
    const float* x      = (const float*)d_in[0];
    const float* values = (const float*)d_in[1];
    float* out = (float*)d_out;
    int n = in_sizes[0];

    int n8 = (n + 7) / 8;
    int threads = 256;
    int per_block = threads * 2;
    int blocks = (n8 + per_block - 1) / per_block;
    if (blocks < 1) blocks = 1;
    gql_kernel<<<blocks, threads>>>(x, values, out, n);
}

// round 14
// speedup vs baseline: 1.0236x; 1.0171x over previous
#include <cuda_runtime.h>
#include <cuda_bf16.h>
#include <cstdint>

// GlobalQuantizedLatent: per-element scalar quantization vs 16-entry codebook.
// Output = 4 contiguous fp32 streams [x, quantized, z_hat, indices(float)].
//
// FINAL — converged at the HBM roofline (13-round lever sweep).
// Identical-binary repeats (n=4): harness 55.1 +- 0.5us, kernel 49.8 +- 0.35us,
// DRAM-active 69.3-70.6%. All structural variants (width 32/128/256b, MLP
// 1/2/4, flat/persistent, 128-512 threads, store orderings, +-.cs) land in
// 67-70.6% DRAM with L2<=48%, issue<=31% idle: the 1:4 R:W-mix HBM ceiling
// (~6.5TB/s effective on 320MB mandatory traffic).
//
//  - 256 threads/block, 2 front-batched independent float8 chunks per thread
//  - 256-bit (.v8) global loads/stores with evict-first .cs hints
//  - x-passthrough store issued immediately after each load (overlaps compute)
//  - exact argmin: candidate k0 = round((x+0.5)*15), first-min-wins tie-break
//    over {k0-1,k0,k0+1} == jnp.argmin over all 16 values (rel_err = 0.0)
//
// Audited-and-rejected: CE-offload copy (384MB total -> ~59us), TMA stores
// (LTS path-independent), zh:=q shortcut (zero traffic delta), arithmetic
// codebook (ALU not binding), occupancy forcing (32-81% occ flat).

__device__ __forceinline__ void ld256cs(const float* __restrict__ p, float* v) {
    asm volatile("ld.global.cs.v8.f32 {%0,%1,%2,%3,%4,%5,%6,%7}, [%8];"
                 : "=f"(v[0]), "=f"(v[1]), "=f"(v[2]), "=f"(v[3]),
                   "=f"(v[4]), "=f"(v[5]), "=f"(v[6]), "=f"(v[7])
                 : "l"(p));
}

__device__ __forceinline__ void st256cs(float* __restrict__ p, const float* v) {
    asm volatile("st.global.cs.v8.f32 [%0], {%1,%2,%3,%4,%5,%6,%7,%8};"
                 :: "l"(p),
                    "f"(v[0]), "f"(v[1]), "f"(v[2]), "f"(v[3]),
                    "f"(v[4]), "f"(v[5]), "f"(v[6]), "f"(v[7])
                 : "memory");
}

__device__ __forceinline__ int quantize_one(float x, const float* __restrict__ sv,
                                            float& q_out) {
    float s = __fmaf_rn(x, 15.0f, 7.5f);      // (x + 0.5) * 15
    int k0 = __float2int_rn(s);
    k0 = min(max(k0, 0), 15);
    int km = max(k0 - 1, 0);
    int kp = min(k0 + 1, 15);

    // first-min-wins argmin over {km,k0,kp} == jnp.argmin over all 16
    float vkm = sv[km], vk0 = sv[k0], vkp = sv[kp];
    float dbest = fabsf(x - vkm);
    int   bi    = km;
    float qv    = vkm;

    float d1 = fabsf(x - vk0);
    if (d1 < dbest) { dbest = d1; bi = k0; qv = vk0; }

    float d2 = fabsf(x - vkp);
    if (d2 < dbest) { bi = kp; qv = vkp; }

    q_out = qv;
    return bi;
}

__device__ __forceinline__ void emit8_rest(float* __restrict__ out_q,
                                           float* __restrict__ out_zh,
                                           float* __restrict__ out_idx,
                                           int base, const float* xv,
                                           const float* __restrict__ sv) {
    float qv[8], zh[8], iv[8];
    #pragma unroll
    for (int j = 0; j < 8; j++) {
        int b = quantize_one(xv[j], sv, qv[j]);
        zh[j] = __fadd_rn(xv[j], __fsub_rn(qv[j], xv[j]));
        iv[j] = (float)b;
    }
    st256cs(out_q   + base, qv);
    st256cs(out_zh  + base, zh);
    st256cs(out_idx + base, iv);
}

__global__ void __launch_bounds__(256)
gql_kernel(const float* __restrict__ x,
           const float* __restrict__ values,
           float* __restrict__ out,
           int n)
{
    __shared__ float sv[16];
    if (threadIdx.x < 16) sv[threadIdx.x] = values[threadIdx.x];
    __syncthreads();

    float* __restrict__ out_x   = out;
    float* __restrict__ out_q   = out + (size_t)n;
    float* __restrict__ out_zh  = out + 2 * (size_t)n;
    float* __restrict__ out_idx = out + 3 * (size_t)n;

    const int n8 = n >> 3;
    int i8a = blockIdx.x * (blockDim.x * 2) + threadIdx.x;   // float8 index
    int i8b = i8a + blockDim.x;
    const int basea = i8a * 8;
    const int baseb = i8b * 8;

    bool va = (i8a < n8), vb = (i8b < n8);
    float xa[8], xb[8];
    // front-batched loads (MLP = 2)
    if (va) ld256cs(x + basea, xa);
    if (vb) ld256cs(x + baseb, xb);

    // passthrough stores depend only on the loads — issue before compute
    if (va) st256cs(out_x + basea, xa);
    if (vb) st256cs(out_x + baseb, xb);

    if (va) emit8_rest(out_q, out_zh, out_idx, basea, xa, sv);
    if (vb) emit8_rest(out_q, out_zh, out_idx, baseb, xb, sv);

    // scalar tail (n not divisible by 8) — not hit for N=16M
    if (blockIdx.x == 0 && threadIdx.x < (n & 7)) {
        int t = (n8 << 3) + threadIdx.x;
        float xi = x[t];
        float q;
        int b = quantize_one(xi, sv, q);
        out_x[t]   = xi;
        out_q[t]   = q;
        out_zh[t]  = __fadd_rn(xi, __fsub_rn(q, xi));
        out_idx[t] = (float)b;
    }
}

extern "C" void kernel_launch(void* const* d_in, const int* in_sizes, int n_in,
                              void* d_out, int out_size) {
    const float* x      = (const float*)d_in[0];
    const float* values = (const float*)d_in[1];
    float* out = (float*)d_out;
    int n = in_sizes[0];

    int n8 = (n + 7) / 8;
    int threads = 256;
    int per_block = threads * 2;
    int blocks = (n8 + per_block - 1) / per_block;
    if (blocks < 1) blocks = 1;
    gql_kernel<<<blocks, threads>>>(x, values, out, n);
}